// round 17
// baseline (speedup 1.0000x reference)
#include <cuda_runtime.h>
#include <cuda_bf16.h>
#include <mma.h>
#include <cstdint>

using namespace nvcuda;

#define B_DIM 128
#define K_DIM 2048
#define D_DIM 512

// GEMM tiling
#define BM 64                // batch rows per block
#define BN 32                // k cols per block
#define GD 256               // d-range per warpgroup (2 groups cover 512)
#define DCW 32               // d per stage
#define NST (GD / DCW)       // 8 stages per group
#define PITCH 40             // bf16 per smem row (32 + 8 pad) = 80B
#define THREADS 512

// per-buffer layout (bf16 elems): XH 64x40, XL 64x40, PH/PL/AH/AL 32x40
#define XH_B 0
#define XL_B (64 * PITCH)
#define PH_B (128 * PITCH)
#define PL_B (160 * PITCH)
#define AH_B (192 * PITCH)
#define AL_B (224 * PITCH)
#define BUF_ELEMS (256 * PITCH)          // 10240 bf16 = 20480 B
// 4 buffers: group g uses {2g, 2g+1}. C aliased over buffers (dead by then):
// C = f32 [2 grp][2 mat][64*32] = 32768 B  <  4*BUF = 81920 B
#define SMEM_BYTES (4 * BUF_ELEMS * 2)   // 81920 B

// ---------------------------------------------------------------------------
// Device-global scratch (no cudaMalloc allowed)
// ---------------------------------------------------------------------------
__device__ float g_uu[K_DIM];
__device__ float g_ua[K_DIM];
__device__ float g_a2[K_DIM];
__device__ float g_vv[B_DIM];
__device__ __nv_bfloat16 g_ph[K_DIM * D_DIM];
__device__ __nv_bfloat16 g_pl[K_DIM * D_DIM];
__device__ __nv_bfloat16 g_ah[K_DIM * D_DIM];
__device__ __nv_bfloat16 g_al[K_DIM * D_DIM];
__device__ __nv_bfloat16 g_xh[B_DIM * D_DIM];
__device__ __nv_bfloat16 g_xl[B_DIM * D_DIM];

struct __align__(8) bh4 { __nv_bfloat162 a, b; };

__device__ __forceinline__ void split4(float4 v, __nv_bfloat16* hi,
                                       __nv_bfloat16* lo, int idx) {
    __nv_bfloat16 h0 = __float2bfloat16_rn(v.x);
    __nv_bfloat16 h1 = __float2bfloat16_rn(v.y);
    __nv_bfloat16 h2 = __float2bfloat16_rn(v.z);
    __nv_bfloat16 h3 = __float2bfloat16_rn(v.w);
    bh4 H; H.a = __nv_bfloat162(h0, h1); H.b = __nv_bfloat162(h2, h3);
    *(bh4*)(hi + idx) = H;
    bh4 L;
    L.a = __nv_bfloat162(__float2bfloat16_rn(v.x - __bfloat162float(h0)),
                         __float2bfloat16_rn(v.y - __bfloat162float(h1)));
    L.b = __nv_bfloat162(__float2bfloat16_rn(v.z - __bfloat162float(h2)),
                         __float2bfloat16_rn(v.w - __bfloat162float(h3)));
    *(bh4*)(lo + idx) = L;
}

// ---------------------------------------------------------------------------
// Kernel 1: per-row stats (fp32) + bf16 hi/lo split of p, a, x.
// ---------------------------------------------------------------------------
__global__ void stats_split_kernel(const float* __restrict__ inp,
                                   const float* __restrict__ p,
                                   const float* __restrict__ a) {
    int warp = (blockIdx.x * blockDim.x + threadIdx.x) >> 5;
    int lane = threadIdx.x & 31;

    if (warp < K_DIM) {
        const float4* pr = (const float4*)(p + warp * D_DIM);
        const float4* ar = (const float4*)(a + warp * D_DIM);
        float pp = 0.f, pa = 0.f, aa = 0.f;
#pragma unroll
        for (int i = 0; i < D_DIM / 128; i++) {
            float4 pv = pr[lane + i * 32];
            float4 av = ar[lane + i * 32];
            pp += pv.x * pv.x + pv.y * pv.y + pv.z * pv.z + pv.w * pv.w;
            pa += pv.x * av.x + pv.y * av.y + pv.z * av.z + pv.w * av.w;
            aa += av.x * av.x + av.y * av.y + av.z * av.z + av.w * av.w;
            int idx = warp * D_DIM + (lane + i * 32) * 4;
            split4(pv, g_ph, g_pl, idx);
            split4(av, g_ah, g_al, idx);
        }
#pragma unroll
        for (int off = 16; off > 0; off >>= 1) {
            pp += __shfl_xor_sync(0xFFFFFFFFu, pp, off);
            pa += __shfl_xor_sync(0xFFFFFFFFu, pa, off);
            aa += __shfl_xor_sync(0xFFFFFFFFu, aa, off);
        }
        if (lane == 0) {
            g_uu[warp] = pp;
            g_ua[warp] = -pa;
            g_a2[warp] = aa;
        }
    } else if (warp < K_DIM + B_DIM) {
        int b = warp - K_DIM;
        const float4* xr = (const float4*)(inp + b * D_DIM);
        float vv = 0.f;
#pragma unroll
        for (int i = 0; i < D_DIM / 128; i++) {
            float4 xv = xr[lane + i * 32];
            vv += xv.x * xv.x + xv.y * xv.y + xv.z * xv.z + xv.w * xv.w;
            split4(xv, g_xh, g_xl, b * D_DIM + (lane + i * 32) * 4);
        }
#pragma unroll
        for (int off = 16; off > 0; off >>= 1)
            vv += __shfl_xor_sync(0xFFFFFFFFu, vv, off);
        if (lane == 0) g_vv[b] = vv;
    }
}

// cp.async helpers
__device__ __forceinline__ void cp16(void* dst, const void* src) {
    unsigned saddr = (unsigned)__cvta_generic_to_shared(dst);
    asm volatile("cp.async.cg.shared.global [%0], [%1], 16;\n"
                 :: "r"(saddr), "l"(src));
}
__device__ __forceinline__ void cp_commit() {
    asm volatile("cp.async.commit_group;\n" ::: "memory");
}
__device__ __forceinline__ void cp_wait1() {
    asm volatile("cp.async.wait_group 1;\n" ::: "memory");
}
__device__ __forceinline__ void cp_wait0() {
    asm volatile("cp.async.wait_group 0;\n" ::: "memory");
}
// named barrier for one warpgroup (256 threads)
__device__ __forceinline__ void gbar(int id) {
    asm volatile("bar.sync %0, 256;" :: "r"(id) : "memory");
}

// ---------------------------------------------------------------------------
// Kernel 2: bf16 WMMA dual GEMM (3-term fp32-emulation) + MLR epilogue.
// Grid (K/BN, B/BM) = (64, 2) = 128 blocks, 512 threads (16 warps).
// Warpgroup g accumulates the same 64x32 tile over d in [256g, 256g+256),
// own double-buffered cp.async stream, named-barrier sync (id g+1).
// Within a group: warps 0-3 -> P-GEMM rows [16w,16w+16) x 32 cols (2 N-frags,
// 2 independent acc chains), warps 4-7 -> A-GEMM.
// 3-term: acc += xh@Wh + xl@Wh + xh@Wl.
// ---------------------------------------------------------------------------
__global__ __launch_bounds__(THREADS, 2)
void hyper_logits_wmma(float* __restrict__ out) {
    extern __shared__ __align__(16) __nv_bfloat16 smb[];
    float* C = (float*)smb;             // aliased over buffers (used after loop)

    const int tid = threadIdx.x;
    const int grp = tid >> 8;           // warpgroup 0/1
    const int gt = tid & 255;           // id within group
    const int warp = gt >> 5;           // 0..7 within group
    const int mat = warp >> 2;          // 0: P-GEMM, 1: A-GEMM
    const int wb = warp & 3;            // b-row group (16 rows)
    const int kbase = blockIdx.x * BN;
    const int bbase = blockIdx.y * BM;
    const int dbase = grp * GD;

    // ---- stage copy: 4 cp16 per thread (group-local) ----
    // X hi: 64 rows x 4 chunks = 256; X lo: 256; W: 4 arrays x 32 rows x 4 = 512.
    auto copy_stage = [&](int s) {
        __nv_bfloat16* buf = smb + (grp * 2 + (s & 1)) * BUF_ELEMS;
        const int d0 = dbase + s * DCW;
        {   // X hi + lo
            int row = gt >> 2, c8 = (gt & 3) * 8;
            size_t g = (size_t)(bbase + row) * D_DIM + d0 + c8;
            int so = row * PITCH + c8;
            cp16(buf + XH_B + so, g_xh + g);
            cp16(buf + XL_B + so, g_xl + g);
        }
        {   // weights: 2 of 4 arrays per thread-half
            int arr2 = gt >> 7, r = gt & 127;       // arr2: 0 -> ph/pl, 1 -> ah/al
            int row = r >> 2, c8 = (r & 3) * 8;
            size_t g = (size_t)(kbase + row) * D_DIM + d0 + c8;
            int so = row * PITCH + c8;
            if (arr2 == 0) {
                cp16(buf + PH_B + so, g_ph + g);
                cp16(buf + PL_B + so, g_pl + g);
            } else {
                cp16(buf + AH_B + so, g_ah + g);
                cp16(buf + AL_B + so, g_al + g);
            }
        }
    };

    wmma::fragment<wmma::accumulator, 16, 16, 16, float> acc0, acc1;
    wmma::fill_fragment(acc0, 0.0f);
    wmma::fill_fragment(acc1, 0.0f);

    copy_stage(0);
    cp_commit();

    for (int t = 0; t < NST; t++) {
        if (t + 1 < NST) {
            copy_stage(t + 1);
            cp_commit();
            cp_wait1();
        } else {
            cp_wait0();
        }
        gbar(grp + 1);

        const __nv_bfloat16* buf = smb + (grp * 2 + (t & 1)) * BUF_ELEMS;
        const __nv_bfloat16* xh = buf + XH_B + wb * 16 * PITCH;
        const __nv_bfloat16* xl = buf + XL_B + wb * 16 * PITCH;
        const __nv_bfloat16* wh = buf + (mat ? AH_B : PH_B);
        const __nv_bfloat16* wl = buf + (mat ? AL_B : PL_B);

#pragma unroll
        for (int cc = 0; cc < DCW / 16; cc++) {
            const int dcol = cc * 16;
            wmma::fragment<wmma::matrix_a, 16, 16, 16, __nv_bfloat16,
                           wmma::row_major> aH, aL;
            wmma::fragment<wmma::matrix_b, 16, 16, 16, __nv_bfloat16,
                           wmma::col_major> bH0, bH1, bL0, bL1;
            wmma::load_matrix_sync(aH, xh + dcol, PITCH);
            wmma::load_matrix_sync(aL, xl + dcol, PITCH);
            wmma::load_matrix_sync(bH0, wh + dcol, PITCH);
            wmma::load_matrix_sync(bH1, wh + 16 * PITCH + dcol, PITCH);
            wmma::load_matrix_sync(bL0, wl + dcol, PITCH);
            wmma::load_matrix_sync(bL1, wl + 16 * PITCH + dcol, PITCH);

            wmma::mma_sync(acc0, aH, bH0, acc0);
            wmma::mma_sync(acc1, aH, bH1, acc1);
            wmma::mma_sync(acc0, aL, bH0, acc0);
            wmma::mma_sync(acc1, aL, bH1, acc1);
            wmma::mma_sync(acc0, aH, bL0, acc0);
            wmma::mma_sync(acc1, aH, bL1, acc1);
        }
        gbar(grp + 1);
    }

    // Both groups fully done with stage buffers before aliasing them as C.
    __syncthreads();

    // ---- dump partials: plane (grp*2+mat), 64x32 row-major ----
    {
        float* cp = C + (grp * 2 + mat) * 2048 + wb * 16 * 32;
        wmma::store_matrix_sync(cp,      acc0, 32, wmma::mem_row_major);
        wmma::store_matrix_sync(cp + 16, acc1, 32, wmma::mem_row_major);
    }
    __syncthreads();

    // ---- epilogue: 64x32 = 2048 logits, 4 per thread; sum D-halves ----
#pragma unroll
    for (int i = 0; i < 4; i++) {
        int idx = tid + THREADS * i;                // 0..2047
        int r = idx >> 5;                           // local b row 0..63
        int c = idx & 31;                           // local k col
        const int b = bbase + r;
        const int k = kbase + c;

        float xp = C[idx] + C[2 * 2048 + idx];          // g0P + g1P
        float xa = C[2048 + idx] + C[3 * 2048 + idx];   // g0A + g1A

        const float uu = g_uu[k];
        const float ua = g_ua[k];
        const float an = sqrtf(g_a2[k]);
        const float coef = 2.0f / (1.0f - uu) * an;
        const float beta = 1.0f - uu;
        const float vv = g_vv[b];

        float uv = -xp;                             // <u,x> = -<p,x>
        float alpha = 1.0f + 2.0f * uv + vv;
        float den   = 1.0f + 2.0f * uv + uu * vv;
        float inv   = 1.0f / den;
        float wa = (alpha * ua + beta * xa) * inv;
        float ww = (alpha * alpha * uu + 2.0f * alpha * beta * uv
                    + beta * beta * vv) * (inv * inv);
        out[b * K_DIM + k] = coef * asinhf(2.0f * wa / (an * (1.0f - ww)));
    }
}

// ---------------------------------------------------------------------------
extern "C" void kernel_launch(void* const* d_in, const int* in_sizes, int n_in,
                              void* d_out, int out_size) {
    const float* inp = (const float*)d_in[0];   // [B, D]
    const float* p   = (const float*)d_in[1];   // [K, D]
    const float* a   = (const float*)d_in[2];   // [K, D]
    float* out = (float*)d_out;                 // [B, K]

    static bool attr_set = false;
    if (!attr_set) {
        cudaFuncSetAttribute(hyper_logits_wmma,
                             cudaFuncAttributeMaxDynamicSharedMemorySize,
                             SMEM_BYTES);
        attr_set = true;
    }

    int nwarps = K_DIM + B_DIM;
    int blocks1 = (nwarps * 32 + 255) / 256;
    stats_split_kernel<<<blocks1, 256>>>(inp, p, a);

    dim3 grid(K_DIM / BN, B_DIM / BM);   // (64, 2) = 128 blocks
    hyper_logits_wmma<<<grid, THREADS, SMEM_BYTES>>>(out);
}